// round 10
// baseline (speedup 1.0000x reference)
#include <cuda_runtime.h>
#include <cuda_bf16.h>
#include <cstdint>
#include <cstddef>

#define NB 64
#define LS 128

__device__ __forceinline__ float sigm(float x){ return 1.0f/(1.0f+__expf(-x)); }
__device__ __forceinline__ uint32_t smem_u32(const void* p){
    uint32_t a; asm("{ .reg .u64 t; cvta.to.shared.u64 t, %1; cvt.u32.u64 %0, t; }"
                    : "=r"(a) : "l"(p)); return a; }

// split pair (f0,f1) -> hi bf16x2, lo-residual bf16x2
__device__ __forceinline__ uint2 split2(float f0, float f1){
    __nv_bfloat162 h2 = __floats2bfloat162_rn(f0, f1);
    uint32_t u = *(uint32_t*)&h2;
    float b0 = __uint_as_float(u << 16);
    float b1 = __uint_as_float(u & 0xffff0000u);
    __nv_bfloat162 l2 = __floats2bfloat162_rn(f0 - b0, f1 - b1);
    uint2 r; r.x = u; r.y = *(uint32_t*)&l2;
    return r;
}
__device__ __forceinline__ void ldm4(uint32_t* r, uint32_t addr){
    asm volatile("ldmatrix.sync.aligned.m8n8.x4.shared.b16 {%0,%1,%2,%3}, [%4];"
        : "=r"(r[0]),"=r"(r[1]),"=r"(r[2]),"=r"(r[3]) : "r"(addr));
}
__device__ __forceinline__ void ldm4t(uint32_t* r, uint32_t addr){
    asm volatile("ldmatrix.sync.aligned.m8n8.x4.trans.shared.b16 {%0,%1,%2,%3}, [%4];"
        : "=r"(r[0]),"=r"(r[1]),"=r"(r[2]),"=r"(r[3]) : "r"(addr));
}
__device__ __forceinline__ void mma16816(float* d, const uint32_t* a, uint32_t b0, uint32_t b1){
    asm volatile("mma.sync.aligned.m16n8k16.row.col.f32.bf16.bf16.f32 "
        "{%0,%1,%2,%3}, {%4,%5,%6,%7}, {%8,%9}, {%0,%1,%2,%3};"
        : "+f"(d[0]),"+f"(d[1]),"+f"(d[2]),"+f"(d[3])
        : "r"(a[0]),"r"(a[1]),"r"(a[2]),"r"(a[3]), "r"(b0),"r"(b1));
}
// lane address into 16x16 block of row-major bf16 array, row stride 72 elems
__device__ __forceinline__ uint32_t fraddr(uint32_t base, int row0, int col0, int lane){
    int grp = lane >> 3, lr = lane & 7;
    int row = row0 + lr + (grp & 1) * 8;
    int col = col0 + (grp >> 1) * 8;
    return base + (uint32_t)(row * 72 + col) * 2u;
}

// ================= fused kernel smem map (bytes) =================
// HB0 0 (hi 9216 | lo 9216) | HB1 18432 | XS 36864 (hi 9216 | lo 9216)
// U2H 55296 | U2L 82944 | W2H 110592 | W2L 138240 | EP 165888 (49152)
#define F_HB0 0u
#define F_HB1 18432u
#define F_XS  36864u
#define F_U2H 55296u
#define F_U2L 82944u
#define F_W2H 110592u
#define F_W2L 138240u
#define F_EP  165888u
#define F_BYTES 215040u

__global__ void __launch_bounds__(384,1) __cluster_dims__(2,1,1) fused_lstm(
    const float* __restrict__ x,   const float* __restrict__ Ww1,
    const float* __restrict__ Ww2, const float* __restrict__ Wu1,
    const float* __restrict__ Wu2, float* __restrict__ out)
{
    extern __shared__ char sb[];
    const uint32_t s0 = smem_u32(sb);
    float* smf = (float*)sb;
    const int tid = threadIdx.x, wid = tid >> 5, lane = tid & 31;
    uint32_t rk; asm("mov.u32 %0, %%cluster_ctarank;" : "=r"(rk));
    const int n  = blockIdx.x >> 1;
    const int A0 = (int)rk * 32;
    const int EPf = 41472;                       // float index of EP

    const int g  = wid >> 2;          // 0..2
    const int rb = (wid >> 1) & 1;    // rowblock16 within own 32 rows
    const int jh = wid & 1;           // j half

    // ---- init: Wu2t / Ww2t split (full, tid<192) ----
    if (tid < 192){
        const int gg = tid >> 6, j = tid & 63;
        float w[64];
        #pragma unroll 4
        for (int b = 0; b < 64; b++) w[b] = Wu2[gg*4096 + b*64 + j];
        uint32_t eb = (uint32_t)((gg*64 + j) * 72);
        #pragma unroll
        for (int k = 0; k < 32; k++){
            uint2 hl = split2(w[2*k], w[2*k+1]);
            *(uint32_t*)(sb + F_U2H + (eb + 2*k)*2) = hl.x;
            *(uint32_t*)(sb + F_U2L + (eb + 2*k)*2) = hl.y;
        }
        #pragma unroll 4
        for (int b = 0; b < 64; b++) w[b] = Ww2[gg*4096 + b*64 + j];
        #pragma unroll
        for (int k = 0; k < 32; k++){
            uint2 hl = split2(w[2*k], w[2*k+1]);
            *(uint32_t*)(sb + F_W2H + (eb + 2*k)*2) = hl.x;
            *(uint32_t*)(sb + F_W2L + (eb + 2*k)*2) = hl.y;
        }
    }

    // ---- Wu1 own-rows split into EP temp -> register fragments ----
    uint32_t AhU[4][4], AlU[4][4], AhW[4][4], AlW[4][4];
    if (tid < 96){
        const int gg = tid >> 5, a = tid & 31;
        float w[64];
        #pragma unroll
        for (int q = 0; q < 16; q++)
            ((float4*)w)[q] = ((const float4*)(Wu1 + (size_t)(gg*64 + A0 + a)*64))[q];
        uint32_t eb = (uint32_t)((gg*32 + a) * 72);
        #pragma unroll
        for (int k = 0; k < 32; k++){
            uint2 hl = split2(w[2*k], w[2*k+1]);
            *(uint32_t*)(sb + F_EP + (eb + 2*k)*2) = hl.x;
            *(uint32_t*)(sb + F_EP + 13824u + (eb + 2*k)*2) = hl.y;
        }
    }
    __syncthreads();
    #pragma unroll
    for (int kc = 0; kc < 4; kc++){
        ldm4(AhU[kc], fraddr(s0 + F_EP,          g*32 + rb*16, kc*16, lane));
        ldm4(AlU[kc], fraddr(s0 + F_EP + 13824u, g*32 + rb*16, kc*16, lane));
    }
    __syncthreads();
    // ---- Ww1 own-rows split into EP temp -> register fragments ----
    if (tid < 96){
        const int gg = tid >> 5, a = tid & 31;
        float w[64];
        #pragma unroll
        for (int q = 0; q < 16; q++)
            ((float4*)w)[q] = ((const float4*)(Ww1 + (size_t)(gg*64 + A0 + a)*64))[q];
        uint32_t eb = (uint32_t)((gg*32 + a) * 72);
        #pragma unroll
        for (int k = 0; k < 32; k++){
            uint2 hl = split2(w[2*k], w[2*k+1]);
            *(uint32_t*)(sb + F_EP + (eb + 2*k)*2) = hl.x;
            *(uint32_t*)(sb + F_EP + 13824u + (eb + 2*k)*2) = hl.y;
        }
    }
    __syncthreads();
    #pragma unroll
    for (int kc = 0; kc < 4; kc++){
        ldm4(AhW[kc], fraddr(s0 + F_EP,          g*32 + rb*16, kc*16, lane));
        ldm4(AlW[kc], fraddr(s0 + F_EP + 13824u, g*32 + rb*16, kc*16, lane));
    }
    __syncthreads();

    // ---- zero both h buffers (36864 B) ----
    for (int i = tid; i < 9216; i += 384) ((uint32_t*)sb)[i] = 0;

    // ---- preload + convert x[n,0] into XS ----
    const int xi = tid >> 2, xj = (tid & 3) * 16;
    if (tid < 256){
        float v[16];
        const float4* s = (const float4*)(x + ((size_t)(n*LS + 0))*4096 + xi*64 + xj);
        #pragma unroll
        for (int q = 0; q < 4; q++) ((float4*)v)[q] = s[q];
        uint32_t eb = (uint32_t)(xi*72 + xj);
        #pragma unroll
        for (int k = 0; k < 8; k++){
            uint2 hl = split2(v[2*k], v[2*k+1]);
            *(uint32_t*)(sb + F_XS + (eb + 2*k)*2)         = hl.x;
            *(uint32_t*)(sb + F_XS + 9216u + (eb + 2*k)*2) = hl.y;
        }
    }
    __syncthreads();

    const uint32_t u2hB = s0 + F_U2H + (uint32_t)g * 9216u;
    const uint32_t u2lB = s0 + F_U2L + (uint32_t)g * 9216u;
    const uint32_t w2hB = s0 + F_W2H + (uint32_t)g * 9216u;
    const uint32_t w2lB = s0 + F_W2L + (uint32_t)g * 9216u;

    const int e_r = tid >> 3, e_c = (tid & 7) * 8;
    float cst[8];
    #pragma unroll
    for (int k = 0; k < 8; k++) cst[k] = 0.0f;

    uint32_t pb;   // peer smem base
    asm("mapa.shared::cluster.u32 %0, %1, %2;" : "=r"(pb) : "r"(s0), "r"(rk^1u));

    asm volatile("barrier.cluster.arrive.aligned;" ::: "memory");
    asm volatile("barrier.cluster.wait.aligned;" ::: "memory");

    int hb = 0;
    for (int t = 0; t < LS; t++){
        // issue x[n,t+1] LDG early (consumed in epilogue)
        float xr[16];
        if (t + 1 < LS && tid < 256){
            const float4* s = (const float4*)(x + ((size_t)(n*LS + t + 1))*4096 + xi*64 + xj);
            #pragma unroll
            for (int q = 0; q < 4; q++) ((float4*)xr)[q] = s[q];
        }

        const uint32_t hsH = s0 + (uint32_t)hb*18432u;
        const uint32_t hsL = hsH + 9216u;

        // ---- stage1-h: D = Wu1[g,own16] @ h[hb] (jh-half of j) ----
        float D[4][4];
        #pragma unroll
        for (int q = 0; q < 4; q++){ D[q][0]=D[q][1]=D[q][2]=D[q][3]=0.0f; }
        #pragma unroll
        for (int kc = 0; kc < 4; kc++){
            #pragma unroll
            for (int nb = 0; nb < 2; nb++){
                uint32_t Bh[4], Bl[4];
                ldm4t(Bh, fraddr(hsH, kc*16, (jh*2+nb)*16, lane));
                ldm4t(Bl, fraddr(hsL, kc*16, (jh*2+nb)*16, lane));
                mma16816(D[2*nb],   AhU[kc], Bh[0], Bh[1]);
                mma16816(D[2*nb+1], AhU[kc], Bh[2], Bh[3]);
                mma16816(D[2*nb],   AhU[kc], Bl[0], Bl[1]);
                mma16816(D[2*nb+1], AhU[kc], Bl[2], Bl[3]);
                mma16816(D[2*nb],   AlU[kc], Bh[0], Bh[1]);
                mma16816(D[2*nb+1], AlU[kc], Bh[2], Bh[3]);
            }
        }
        uint32_t A2h[2][4], A2l[2][4];
        #pragma unroll
        for (int c = 0; c < 2; c++){
            uint2 p0 = split2(D[2*c][0],   D[2*c][1]);
            uint2 p1 = split2(D[2*c][2],   D[2*c][3]);
            uint2 p2 = split2(D[2*c+1][0], D[2*c+1][1]);
            uint2 p3 = split2(D[2*c+1][2], D[2*c+1][3]);
            A2h[c][0]=p0.x; A2h[c][1]=p1.x; A2h[c][2]=p2.x; A2h[c][3]=p3.x;
            A2l[c][0]=p0.y; A2l[c][1]=p1.y; A2l[c][2]=p2.y; A2l[c][3]=p3.y;
        }

        // ---- stage1-x: D = Ww1[g,own16] @ x[t] (jh-half of j) ----
        #pragma unroll
        for (int q = 0; q < 4; q++){ D[q][0]=D[q][1]=D[q][2]=D[q][3]=0.0f; }
        #pragma unroll
        for (int kc = 0; kc < 4; kc++){
            #pragma unroll
            for (int nb = 0; nb < 2; nb++){
                uint32_t Bh[4], Bl[4];
                ldm4t(Bh, fraddr(s0 + F_XS,         kc*16, (jh*2+nb)*16, lane));
                ldm4t(Bl, fraddr(s0 + F_XS + 9216u, kc*16, (jh*2+nb)*16, lane));
                mma16816(D[2*nb],   AhW[kc], Bh[0], Bh[1]);
                mma16816(D[2*nb+1], AhW[kc], Bh[2], Bh[3]);
                mma16816(D[2*nb],   AhW[kc], Bl[0], Bl[1]);
                mma16816(D[2*nb+1], AhW[kc], Bl[2], Bl[3]);
                mma16816(D[2*nb],   AlW[kc], Bh[0], Bh[1]);
                mma16816(D[2*nb+1], AlW[kc], Bh[2], Bh[3]);
            }
        }
        uint32_t X2h[2][4], X2l[2][4];
        #pragma unroll
        for (int c = 0; c < 2; c++){
            uint2 p0 = split2(D[2*c][0],   D[2*c][1]);
            uint2 p1 = split2(D[2*c][2],   D[2*c][3]);
            uint2 p2 = split2(D[2*c+1][0], D[2*c+1][1]);
            uint2 p3 = split2(D[2*c+1][2], D[2*c+1][3]);
            X2h[c][0]=p0.x; X2h[c][1]=p1.x; X2h[c][2]=p2.x; X2h[c][3]=p3.x;
            X2l[c][0]=p0.y; X2l[c][1]=p1.y; X2l[c][2]=p2.y; X2l[c][3]=p3.y;
        }

        // ---- stage2 merged: E = T_h @ Wu2t + T_x @ Ww2t (partial over jh) ----
        float E[8][4];
        #pragma unroll
        for (int q = 0; q < 8; q++){ E[q][0]=E[q][1]=E[q][2]=E[q][3]=0.0f; }
        #pragma unroll
        for (int c = 0; c < 2; c++){
            #pragma unroll
            for (int nb = 0; nb < 4; nb++){
                uint32_t Bh[4], Bl[4];
                ldm4t(Bh, fraddr(u2hB, jh*32 + c*16, nb*16, lane));
                ldm4t(Bl, fraddr(u2lB, jh*32 + c*16, nb*16, lane));
                mma16816(E[2*nb],   A2h[c], Bh[0], Bh[1]);
                mma16816(E[2*nb+1], A2h[c], Bh[2], Bh[3]);
                mma16816(E[2*nb],   A2h[c], Bl[0], Bl[1]);
                mma16816(E[2*nb+1], A2h[c], Bl[2], Bl[3]);
                mma16816(E[2*nb],   A2l[c], Bh[0], Bh[1]);
                mma16816(E[2*nb+1], A2l[c], Bh[2], Bh[3]);
                uint32_t Ch[4], Cl[4];
                ldm4t(Ch, fraddr(w2hB, jh*32 + c*16, nb*16, lane));
                ldm4t(Cl, fraddr(w2lB, jh*32 + c*16, nb*16, lane));
                mma16816(E[2*nb],   X2h[c], Ch[0], Ch[1]);
                mma16816(E[2*nb+1], X2h[c], Ch[2], Ch[3]);
                mma16816(E[2*nb],   X2h[c], Cl[0], Cl[1]);
                mma16816(E[2*nb+1], X2h[c], Cl[2], Cl[3]);
                mma16816(E[2*nb],   X2l[c], Ch[0], Ch[1]);
                mma16816(E[2*nb+1], X2l[c], Ch[2], Ch[3]);
            }
        }
        // ---- store E partials ----
        {
            float* dst = smf + EPf + (jh*3 + g)*2048;
            const int r0 = rb*16 + (lane >> 2);
            const int cb = (lane & 3) * 2;
            #pragma unroll
            for (int nb = 0; nb < 4; nb++){
                #pragma unroll
                for (int hf = 0; hf < 2; hf++){
                    int q = 2*nb + hf;
                    int b = nb*16 + hf*8 + cb;
                    float* d2 = dst + r0*64 + b;
                    *(float2*)d2          = make_float2(E[q][0], E[q][1]);
                    *(float2*)(d2 + 8*64) = make_float2(E[q][2], E[q][3]);
                }
            }
        }
        __syncthreads();                  // E visible

        // ---- epilogue ----
        float hv[8];
        if (tid < 256){
            const int be = e_r*64 + e_c;
            #pragma unroll
            for (int k = 0; k < 8; k++){
                float z = sigm(smf[EPf + be + k]        + smf[EPf + 6144 + be + k]);
                float r = sigm(smf[EPf + 2048 + be + k] + smf[EPf + 8192 + be + k]);
                float o = sigm(smf[EPf + 4096 + be + k] + smf[EPf + 10240 + be + k]);
                cst[k] = r * (cst[k] + z);
                hv[k] = o * sigm(cst[k]);
            }
            uint32_t hi[4], lo[4];
            #pragma unroll
            for (int k = 0; k < 4; k++){
                uint2 hl = split2(hv[2*k], hv[2*k+1]);
                hi[k] = hl.x; lo[k] = hl.y;
            }
            const uint32_t hwb = (uint32_t)(hb^1)*18432u;
            const uint32_t ho = (uint32_t)(((A0 + e_r)*72 + e_c) * 2);
            *(uint4*)(sb + hwb + ho)         = make_uint4(hi[0],hi[1],hi[2],hi[3]);
            *(uint4*)(sb + hwb + 9216u + ho) = make_uint4(lo[0],lo[1],lo[2],lo[3]);
            uint64_t h01, h23, l01, l23;
            asm("mov.b64 %0, {%1,%2};" : "=l"(h01) : "r"(hi[0]), "r"(hi[1]));
            asm("mov.b64 %0, {%1,%2};" : "=l"(h23) : "r"(hi[2]), "r"(hi[3]));
            asm("mov.b64 %0, {%1,%2};" : "=l"(l01) : "r"(lo[0]), "r"(lo[1]));
            asm("mov.b64 %0, {%1,%2};" : "=l"(l23) : "r"(lo[2]), "r"(lo[3]));
            asm volatile("st.shared::cluster.b64 [%0], %1;" :: "r"(pb + hwb + ho),             "l"(h01));
            asm volatile("st.shared::cluster.b64 [%0], %1;" :: "r"(pb + hwb + ho + 8),         "l"(h23));
            asm volatile("st.shared::cluster.b64 [%0], %1;" :: "r"(pb + hwb + 9216u + ho),     "l"(l01));
            asm volatile("st.shared::cluster.b64 [%0], %1;" :: "r"(pb + hwb + 9216u + ho + 8), "l"(l23));
            // convert x[t+1] regs -> XS
            if (t + 1 < LS){
                uint32_t eb = (uint32_t)(xi*72 + xj);
                #pragma unroll
                for (int k = 0; k < 8; k++){
                    uint2 hl = split2(xr[2*k], xr[2*k+1]);
                    *(uint32_t*)(sb + F_XS + (eb + 2*k)*2)         = hl.x;
                    *(uint32_t*)(sb + F_XS + 9216u + (eb + 2*k)*2) = hl.y;
                }
            }
        }
        asm volatile("barrier.cluster.arrive.aligned;" ::: "memory");

        if (tid < 256){
            float* od = out + ((size_t)(n*LS + t))*4096 + (A0 + e_r)*64 + e_c;
            *(float4*)(od)   = make_float4(hv[0],hv[1],hv[2],hv[3]);
            *(float4*)(od+4) = make_float4(hv[4],hv[5],hv[6],hv[7]);
            if (t == LS-1){
                float* hl2 = out + (size_t)NB*LS*4096 + (size_t)n*4096 + (A0 + e_r)*64 + e_c;
                *(float4*)(hl2)   = make_float4(hv[0],hv[1],hv[2],hv[3]);
                *(float4*)(hl2+4) = make_float4(hv[4],hv[5],hv[6],hv[7]);
            }
        }
        asm volatile("barrier.cluster.wait.aligned;" ::: "memory");
        hb ^= 1;
    }

    // c_last (own rows)
    if (tid < 256){
        float* cl = out + (size_t)NB*LS*4096 + (size_t)NB*4096
                        + (size_t)n*4096 + (A0 + e_r)*64 + e_c;
        *(float4*)(cl)   = make_float4(cst[0],cst[1],cst[2],cst[3]);
        *(float4*)(cl+4) = make_float4(cst[4],cst[5],cst[6],cst[7]);
    }
}

// ---------------------------------------------------------------------------
extern "C" void kernel_launch(void* const* d_in, const int* in_sizes, int n_in,
                              void* d_out, int out_size)
{
    const float* x   = (const float*)d_in[0];
    const float* Ww1 = (const float*)d_in[1];
    const float* Ww2 = (const float*)d_in[2];
    const float* Wu1 = (const float*)d_in[3];
    const float* Wu2 = (const float*)d_in[4];
    float* out = (float*)d_out;

    cudaFuncSetAttribute(fused_lstm, cudaFuncAttributeMaxDynamicSharedMemorySize, (int)F_BYTES);
    fused_lstm<<<2 * NB, 384, F_BYTES>>>(x, Ww1, Ww2, Wu1, Wu2, out);
}

// round 11
// speedup vs baseline: 1.0489x; 1.0489x over previous
#include <cuda_runtime.h>
#include <cuda_bf16.h>
#include <cstdint>
#include <cstddef>

#define NB 64
#define LS 128

__device__ float g_xg[(size_t)LS*3*NB*4096];

__device__ __forceinline__ float sigm(float x){ return 1.0f/(1.0f+__expf(-x)); }
__device__ __forceinline__ void cpa16(void* dst, const float* src){
    asm volatile("cp.async.ca.shared.global [%0], [%1], 16;"
                 :: "r"((uint32_t)__cvta_generic_to_shared(dst)), "l"(src)); }
__device__ __forceinline__ uint32_t smem_u32(const void* p){
    uint32_t a; asm("{ .reg .u64 t; cvta.to.shared.u64 t, %1; cvt.u32.u64 %0, t; }"
                    : "=r"(a) : "l"(p)); return a; }

// split pair (f0,f1) -> hi bf16x2, lo-residual bf16x2
__device__ __forceinline__ uint2 split2(float f0, float f1){
    __nv_bfloat162 h2 = __floats2bfloat162_rn(f0, f1);
    uint32_t u = *(uint32_t*)&h2;
    float b0 = __uint_as_float(u << 16);
    float b1 = __uint_as_float(u & 0xffff0000u);
    __nv_bfloat162 l2 = __floats2bfloat162_rn(f0 - b0, f1 - b1);
    uint2 r; r.x = u; r.y = *(uint32_t*)&l2;
    return r;
}
__device__ __forceinline__ void ldm4(uint32_t* r, uint32_t addr){
    asm volatile("ldmatrix.sync.aligned.m8n8.x4.shared.b16 {%0,%1,%2,%3}, [%4];"
        : "=r"(r[0]),"=r"(r[1]),"=r"(r[2]),"=r"(r[3]) : "r"(addr));
}
__device__ __forceinline__ void ldm4t(uint32_t* r, uint32_t addr){
    asm volatile("ldmatrix.sync.aligned.m8n8.x4.trans.shared.b16 {%0,%1,%2,%3}, [%4];"
        : "=r"(r[0]),"=r"(r[1]),"=r"(r[2]),"=r"(r[3]) : "r"(addr));
}
__device__ __forceinline__ void mma16816(float* d, const uint32_t* a, uint32_t b0, uint32_t b1){
    asm volatile("mma.sync.aligned.m16n8k16.row.col.f32.bf16.bf16.f32 "
        "{%0,%1,%2,%3}, {%4,%5,%6,%7}, {%8,%9}, {%0,%1,%2,%3};"
        : "+f"(d[0]),"+f"(d[1]),"+f"(d[2]),"+f"(d[3])
        : "r"(a[0]),"r"(a[1]),"r"(a[2]),"r"(a[3]), "r"(b0),"r"(b1));
}
// lane address into 16x16 block of row-major bf16 array, row stride 72 elems
__device__ __forceinline__ uint32_t fraddr(uint32_t base, int row0, int col0, int lane){
    int grp = lane >> 3, lr = lane & 7;
    int row = row0 + lr + (grp & 1) * 8;
    int col = col0 + (grp >> 1) * 8;
    return base + (uint32_t)(row * 72 + col) * 2u;
}

// ===================== Phase 1 (unchanged, verified round 6) =====================
#define P1_XH   0u
#define P1_XL   9216u
#define P1_W1H  18432u
#define P1_W1L  46080u
#define P1_W2H  73728u
#define P1_W2L  101376u
#define P1_BYTES 129024u

__global__ void __launch_bounds__(384,1) phase1_mma(
    const float* __restrict__ x, const float* __restrict__ Ww1,
    const float* __restrict__ Ww2, float* __restrict__ xg)
{
    extern __shared__ char sb[];
    const uint32_t s0 = smem_u32(sb);
    const int tid = threadIdx.x, wid = tid >> 5, lane = tid & 31;

    if (tid < 192){
        const int g = tid >> 6, row = tid & 63;
        float w[64];
        #pragma unroll
        for (int q = 0; q < 16; q++)
            ((float4*)w)[q] = ((const float4*)(Ww1 + tid * 64))[q];
        uint32_t eb = (uint32_t)(g * 4608 + row * 72);
        #pragma unroll
        for (int k = 0; k < 32; k++){
            uint2 hl = split2(w[2*k], w[2*k+1]);
            *(uint32_t*)(sb + P1_W1H + (eb + 2*k)*2) = hl.x;
            *(uint32_t*)(sb + P1_W1L + (eb + 2*k)*2) = hl.y;
        }
        #pragma unroll 4
        for (int b = 0; b < 64; b++) w[b] = Ww2[g * 4096 + b * 64 + row];
        #pragma unroll
        for (int k = 0; k < 32; k++){
            uint2 hl = split2(w[2*k], w[2*k+1]);
            *(uint32_t*)(sb + P1_W2H + (eb + 2*k)*2) = hl.x;
            *(uint32_t*)(sb + P1_W2L + (eb + 2*k)*2) = hl.y;
        }
    }

    const int g  = wid >> 2;
    const int rb = wid & 3;
    const uint32_t w1hB = s0 + P1_W1H + (uint32_t)g * 9216u;
    const uint32_t w1lB = s0 + P1_W1L + (uint32_t)g * 9216u;
    const uint32_t w2hB = s0 + P1_W2H + (uint32_t)g * 9216u;
    const uint32_t w2lB = s0 + P1_W2L + (uint32_t)g * 9216u;

    float4 xr[4];
    const int xi = tid >> 2, xj = (tid & 3) * 16;

    int p = blockIdx.x;
    if (p < NB*LS && tid < 256){
        const float4* s = (const float4*)(x + (size_t)p*4096 + xi*64 + xj);
        xr[0]=s[0]; xr[1]=s[1]; xr[2]=s[2]; xr[3]=s[3];
    }

    for (; p < NB*LS; p += gridDim.x){
        __syncthreads();
        if (tid < 256){
            const float* xf = (const float*)xr;
            uint32_t eb = (uint32_t)(xi * 72 + xj);
            #pragma unroll
            for (int k = 0; k < 8; k++){
                uint2 hl = split2(xf[2*k], xf[2*k+1]);
                *(uint32_t*)(sb + P1_XH + (eb + 2*k)*2) = hl.x;
                *(uint32_t*)(sb + P1_XL + (eb + 2*k)*2) = hl.y;
            }
        }
        __syncthreads();
        int pn = p + gridDim.x;
        if (pn < NB*LS && tid < 256){
            const float4* s = (const float4*)(x + (size_t)pn*4096 + xi*64 + xj);
            xr[0]=s[0]; xr[1]=s[1]; xr[2]=s[2]; xr[3]=s[3];
        }

        float D[8][4];
        #pragma unroll
        for (int t = 0; t < 8; t++){ D[t][0]=D[t][1]=D[t][2]=D[t][3]=0.0f; }
        #pragma unroll
        for (int kc = 0; kc < 4; kc++){
            uint32_t Ah[4], Al[4];
            ldm4(Ah, fraddr(w1hB, rb*16, kc*16, lane));
            ldm4(Al, fraddr(w1lB, rb*16, kc*16, lane));
            #pragma unroll
            for (int nb = 0; nb < 4; nb++){
                uint32_t Bh[4], Bl[4];
                ldm4t(Bh, fraddr(s0 + P1_XH, kc*16, nb*16, lane));
                ldm4t(Bl, fraddr(s0 + P1_XL, kc*16, nb*16, lane));
                mma16816(D[2*nb],   Ah, Bh[0], Bh[1]);
                mma16816(D[2*nb+1], Ah, Bh[2], Bh[3]);
                mma16816(D[2*nb],   Ah, Bl[0], Bl[1]);
                mma16816(D[2*nb+1], Ah, Bl[2], Bl[3]);
                mma16816(D[2*nb],   Al, Bh[0], Bh[1]);
                mma16816(D[2*nb+1], Al, Bh[2], Bh[3]);
            }
        }

        uint32_t A2h[4][4], A2l[4][4];
        #pragma unroll
        for (int kc = 0; kc < 4; kc++){
            uint2 p0 = split2(D[2*kc][0],   D[2*kc][1]);
            uint2 p1 = split2(D[2*kc][2],   D[2*kc][3]);
            uint2 p2 = split2(D[2*kc+1][0], D[2*kc+1][1]);
            uint2 p3 = split2(D[2*kc+1][2], D[2*kc+1][3]);
            A2h[kc][0]=p0.x; A2h[kc][1]=p1.x; A2h[kc][2]=p2.x; A2h[kc][3]=p3.x;
            A2l[kc][0]=p0.y; A2l[kc][1]=p1.y; A2l[kc][2]=p2.y; A2l[kc][3]=p3.y;
        }

        float E[8][4];
        #pragma unroll
        for (int t = 0; t < 8; t++){ E[t][0]=E[t][1]=E[t][2]=E[t][3]=0.0f; }
        #pragma unroll
        for (int kc = 0; kc < 4; kc++){
            #pragma unroll
            for (int nb = 0; nb < 4; nb++){
                uint32_t Bh[4], Bl[4];
                ldm4t(Bh, fraddr(w2hB, kc*16, nb*16, lane));
                ldm4t(Bl, fraddr(w2lB, kc*16, nb*16, lane));
                mma16816(E[2*nb],   A2h[kc], Bh[0], Bh[1]);
                mma16816(E[2*nb+1], A2h[kc], Bh[2], Bh[3]);
                mma16816(E[2*nb],   A2h[kc], Bl[0], Bl[1]);
                mma16816(E[2*nb+1], A2h[kc], Bl[2], Bl[3]);
                mma16816(E[2*nb],   A2l[kc], Bh[0], Bh[1]);
                mma16816(E[2*nb+1], A2l[kc], Bh[2], Bh[3]);
            }
        }

        {
            const int n = p >> 7, l = p & 127;
            float* dst = xg + ((size_t)((l*3+g)*NB + n))*4096;
            const int r0 = rb*16 + (lane >> 2);
            const int cb = (lane & 3) * 2;
            #pragma unroll
            for (int nb = 0; nb < 4; nb++){
                #pragma unroll
                for (int hf = 0; hf < 2; hf++){
                    int t = 2*nb + hf;
                    int b = nb*16 + hf*8 + cb;
                    float* q = dst + r0*64 + b;
                    *(float2*)q          = make_float2(E[t][0], E[t][1]);
                    *(float2*)(q + 8*64) = make_float2(E[t][2], E[t][3]);
                }
            }
        }
    }
}

// ===================== Phase 2 (mma.sync, cluster-2, padded smem) =====================
// h buffers: HB0 at 0, HB1 at 18432 (each: hi 9216 + lo 9216)
// W2H 36864 (27648) | W2L 64512 (27648)
// EP 92160: 6 partials x 32 rows x 68 floats (2176 f each) = 52224 B
// XGS 144384: 2 bufs x 3 gates x 32 rows x 68 floats (6528 f/buf) = 52224 B
#define R2_W2H 36864u
#define R2_W2L 64512u
#define R2_EP  92160u
#define R2_XGS 144384u
#define R2_BYTES 196608u
#define EPS 68            // padded row stride (floats)
#define EPP 2176          // floats per partial (32*68)
#define XGB 6528          // floats per xg buffer (3*2176)

__global__ void __launch_bounds__(384,1) __cluster_dims__(2,1,1) phase2_mma(
    const float* __restrict__ Wu1, const float* __restrict__ Wu2,
    const float* __restrict__ xg, float* __restrict__ out)
{
    extern __shared__ char sb[];
    const uint32_t s0 = smem_u32(sb);
    float* smf = (float*)sb;
    const int tid = threadIdx.x, wid = tid >> 5, lane = tid & 31;
    uint32_t rk; asm("mov.u32 %0, %%cluster_ctarank;" : "=r"(rk));
    const int n  = blockIdx.x >> 1;
    const int A0 = (int)rk * 32;
    const int EPf = 23040, XGSf = 36096;     // float indices

    // ---- init: Wu2t split (full, both CTAs) ----
    if (tid < 192){
        const int g = tid >> 6, j = tid & 63;
        float w[64];
        #pragma unroll 4
        for (int b = 0; b < 64; b++) w[b] = Wu2[g*4096 + b*64 + j];
        uint32_t eb = (uint32_t)((g*64 + j) * 72);
        #pragma unroll
        for (int k = 0; k < 32; k++){
            uint2 hl = split2(w[2*k], w[2*k+1]);
            *(uint32_t*)(sb + R2_W2H + (eb + 2*k)*2) = hl.x;
            *(uint32_t*)(sb + R2_W2L + (eb + 2*k)*2) = hl.y;
        }
    }
    // ---- Wu1 own 32 rows per gate, split into temp (XGS area) ----
    if (tid < 96){
        const int g = tid >> 5, a = tid & 31;
        float w[64];
        #pragma unroll
        for (int q = 0; q < 16; q++)
            ((float4*)w)[q] = ((const float4*)(Wu1 + (size_t)(g*64 + A0 + a)*64))[q];
        uint32_t eb = (uint32_t)((g*32 + a) * 72);
        #pragma unroll
        for (int k = 0; k < 32; k++){
            uint2 hl = split2(w[2*k], w[2*k+1]);
            *(uint32_t*)(sb + R2_XGS + (eb + 2*k)*2) = hl.x;
            *(uint32_t*)(sb + R2_XGS + 13824u + (eb + 2*k)*2) = hl.y;
        }
    }
    // zero both h buffers (2 x 18432 B)
    for (int i = tid; i < 9216; i += 384) ((uint32_t*)sb)[i] = 0;
    __syncthreads();

    // ---- warp task + A-fragment preload (constant over t) ----
    const int g  = wid >> 2;          // 0..2
    const int rb = (wid >> 1) & 1;    // rowblock16 within own 32 rows
    const int jh = wid & 1;           // j half
    uint32_t Ah[4][4], Al[4][4];
    #pragma unroll
    for (int kc = 0; kc < 4; kc++){
        ldm4(Ah[kc], fraddr(s0 + R2_XGS + (uint32_t)g*4608u, rb*16, kc*16, lane));
        ldm4(Al[kc], fraddr(s0 + R2_XGS + 13824u + (uint32_t)g*4608u, rb*16, kc*16, lane));
    }
    __syncthreads();   // temp reads done; XGS reusable

    const uint32_t w2hB = s0 + R2_W2H + (uint32_t)g * 9216u;
    const uint32_t w2lB = s0 + R2_W2L + (uint32_t)g * 9216u;

    // epilogue mapping: 256 threads, 8 cols each over own 32 rows
    const int e_r = tid >> 3, e_c = (tid & 7) * 8;
    float cst[8];
    #pragma unroll
    for (int k = 0; k < 8; k++) cst[k] = 0.0f;

    uint32_t pb;   // peer smem base
    asm("mapa.shared::cluster.u32 %0, %1, %2;" : "=r"(pb) : "r"(s0), "r"(rk^1u));

    // prefetch xg[0] (own rows) into buf 0
    #pragma unroll
    for (int k = 0; k < 4; k++){
        int idx = tid + 384*k;                     // < 1536 chunks
        int gx = idx / 512, rem = idx & 511;
        int row = rem >> 4, off = rem & 15;
        cpa16(smf + XGSf + gx*EPP + row*EPS + off*4,
              xg + ((size_t)((0*3 + gx)*NB + n))*4096 + (A0+row)*64 + off*4);
    }
    asm volatile("cp.async.commit_group;");

    // both CTAs' h buffers zeroed before any peer store
    asm volatile("barrier.cluster.arrive.aligned;" ::: "memory");
    asm volatile("barrier.cluster.wait.aligned;" ::: "memory");

    int buf = 0, hb = 0;
    for (int t = 0; t < LS; t++){
        const uint32_t hsH = s0 + (uint32_t)hb*18432u;
        const uint32_t hsL = hsH + 9216u;

        // ---- stage1: T[16 rows, jh-half] = Wu1[g,own rows] @ h[hb] ----
        float D[4][4];
        #pragma unroll
        for (int q = 0; q < 4; q++){ D[q][0]=D[q][1]=D[q][2]=D[q][3]=0.0f; }
        #pragma unroll
        for (int kc = 0; kc < 4; kc++){
            #pragma unroll
            for (int nb = 0; nb < 2; nb++){
                uint32_t Bh[4], Bl[4];
                ldm4t(Bh, fraddr(hsH, kc*16, (jh*2+nb)*16, lane));
                ldm4t(Bl, fraddr(hsL, kc*16, (jh*2+nb)*16, lane));
                mma16816(D[2*nb],   Ah[kc], Bh[0], Bh[1]);
                mma16816(D[2*nb+1], Ah[kc], Bh[2], Bh[3]);
                mma16816(D[2*nb],   Ah[kc], Bl[0], Bl[1]);
                mma16816(D[2*nb+1], Ah[kc], Bl[2], Bl[3]);
                mma16816(D[2*nb],   Al[kc], Bh[0], Bh[1]);
                mma16816(D[2*nb+1], Al[kc], Bh[2], Bh[3]);
            }
        }
        // ---- repack D -> A2 fragments ----
        uint32_t A2h[2][4], A2l[2][4];
        #pragma unroll
        for (int c = 0; c < 2; c++){
            uint2 p0 = split2(D[2*c][0],   D[2*c][1]);
            uint2 p1 = split2(D[2*c][2],   D[2*c][3]);
            uint2 p2 = split2(D[2*c+1][0], D[2*c+1][1]);
            uint2 p3 = split2(D[2*c+1][2], D[2*c+1][3]);
            A2h[c][0]=p0.x; A2h[c][1]=p1.x; A2h[c][2]=p2.x; A2h[c][3]=p3.x;
            A2l[c][0]=p0.y; A2l[c][1]=p1.y; A2l[c][2]=p2.y; A2l[c][3]=p3.y;
        }
        // ---- stage2 partial ----
        float E[8][4];
        #pragma unroll
        for (int q = 0; q < 8; q++){ E[q][0]=E[q][1]=E[q][2]=E[q][3]=0.0f; }
        #pragma unroll
        for (int c = 0; c < 2; c++){
            #pragma unroll
            for (int nb = 0; nb < 4; nb++){
                uint32_t Bh[4], Bl[4];
                ldm4t(Bh, fraddr(w2hB, jh*32 + c*16, nb*16, lane));
                ldm4t(Bl, fraddr(w2lB, jh*32 + c*16, nb*16, lane));
                mma16816(E[2*nb],   A2h[c], Bh[0], Bh[1]);
                mma16816(E[2*nb+1], A2h[c], Bh[2], Bh[3]);
                mma16816(E[2*nb],   A2h[c], Bl[0], Bl[1]);
                mma16816(E[2*nb+1], A2h[c], Bl[2], Bl[3]);
                mma16816(E[2*nb],   A2l[c], Bh[0], Bh[1]);
                mma16816(E[2*nb+1], A2l[c], Bh[2], Bh[3]);
            }
        }
        // ---- store E partial (padded stride 68 -> conflict-free STS.64) ----
        {
            float* dst = smf + EPf + (jh*3 + g)*EPP;
            const int r0 = rb*16 + (lane >> 2);
            const int cb = (lane & 3) * 2;
            #pragma unroll
            for (int nb = 0; nb < 4; nb++){
                #pragma unroll
                for (int hf = 0; hf < 2; hf++){
                    int q = 2*nb + hf;
                    int b = nb*16 + hf*8 + cb;
                    float* d2 = dst + r0*EPS + b;
                    *(float2*)d2            = make_float2(E[q][0], E[q][1]);
                    *(float2*)(d2 + 8*EPS)  = make_float2(E[q][2], E[q][3]);
                }
            }
        }
        asm volatile("cp.async.wait_group 0;");
        __syncthreads();                  // E + xg[t] visible to all

        // ---- epilogue (h -> h[hb^1], local + peer) ----
        float hv[8];
        if (tid < 256){
            const int be = e_r*EPS + e_c;
            const float* ep = smf + EPf;
            const float* xb = smf + XGSf + buf*XGB;
            float4 za = *(const float4*)(ep + be);
            float4 zb = *(const float4*)(ep + be + 4);
            float4 zc = *(const float4*)(ep + 3*EPP + be);
            float4 zd = *(const float4*)(ep + 3*EPP + be + 4);
            float4 ze = *(const float4*)(xb + be);
            float4 zf = *(const float4*)(xb + be + 4);
            float4 ra = *(const float4*)(ep + 1*EPP + be);
            float4 rb4= *(const float4*)(ep + 1*EPP + be + 4);
            float4 rc = *(const float4*)(ep + 4*EPP + be);
            float4 rd = *(const float4*)(ep + 4*EPP + be + 4);
            float4 re = *(const float4*)(xb + 1*EPP + be);
            float4 rf = *(const float4*)(xb + 1*EPP + be + 4);
            float4 oa = *(const float4*)(ep + 2*EPP + be);
            float4 ob = *(const float4*)(ep + 2*EPP + be + 4);
            float4 oc = *(const float4*)(ep + 5*EPP + be);
            float4 od = *(const float4*)(ep + 5*EPP + be + 4);
            float4 oe = *(const float4*)(xb + 2*EPP + be);
            float4 of = *(const float4*)(xb + 2*EPP + be + 4);
            float zs[8] = {za.x+zc.x+ze.x, za.y+zc.y+ze.y, za.z+zc.z+ze.z, za.w+zc.w+ze.w,
                           zb.x+zd.x+zf.x, zb.y+zd.y+zf.y, zb.z+zd.z+zf.z, zb.w+zd.w+zf.w};
            float rs[8] = {ra.x+rc.x+re.x, ra.y+rc.y+re.y, ra.z+rc.z+re.z, ra.w+rc.w+re.w,
                           rb4.x+rd.x+rf.x, rb4.y+rd.y+rf.y, rb4.z+rd.z+rf.z, rb4.w+rd.w+rf.w};
            float os[8] = {oa.x+oc.x+oe.x, oa.y+oc.y+oe.y, oa.z+oc.z+oe.z, oa.w+oc.w+oe.w,
                           ob.x+od.x+of.x, ob.y+od.y+of.y, ob.z+od.z+of.z, ob.w+od.w+of.w};
            #pragma unroll
            for (int k = 0; k < 8; k++){
                float z = sigm(zs[k]);
                float r = sigm(rs[k]);
                float o = sigm(os[k]);
                cst[k] = r * (cst[k] + z);
                hv[k] = o * sigm(cst[k]);
            }
            uint32_t hi[4], lo[4];
            #pragma unroll
            for (int k = 0; k < 4; k++){
                uint2 hl = split2(hv[2*k], hv[2*k+1]);
                hi[k] = hl.x; lo[k] = hl.y;
            }
            const uint32_t hwb = (uint32_t)(hb^1)*18432u;
            const uint32_t ho = (uint32_t)(((A0 + e_r)*72 + e_c) * 2);
            *(uint4*)(sb + hwb + ho)         = make_uint4(hi[0],hi[1],hi[2],hi[3]);
            *(uint4*)(sb + hwb + 9216u + ho) = make_uint4(lo[0],lo[1],lo[2],lo[3]);
            uint64_t h01, h23, l01, l23;
            asm("mov.b64 %0, {%1,%2};" : "=l"(h01) : "r"(hi[0]), "r"(hi[1]));
            asm("mov.b64 %0, {%1,%2};" : "=l"(h23) : "r"(hi[2]), "r"(hi[3]));
            asm("mov.b64 %0, {%1,%2};" : "=l"(l01) : "r"(lo[0]), "r"(lo[1]));
            asm("mov.b64 %0, {%1,%2};" : "=l"(l23) : "r"(lo[2]), "r"(lo[3]));
            asm volatile("st.shared::cluster.b64 [%0], %1;" :: "r"(pb + hwb + ho),             "l"(h01));
            asm volatile("st.shared::cluster.b64 [%0], %1;" :: "r"(pb + hwb + ho + 8),         "l"(h23));
            asm volatile("st.shared::cluster.b64 [%0], %1;" :: "r"(pb + hwb + 9216u + ho),     "l"(l01));
            asm volatile("st.shared::cluster.b64 [%0], %1;" :: "r"(pb + hwb + 9216u + ho + 8), "l"(l23));
        }
        // arrive (releases the peer-h stores), then overlap STG/prefetch, then wait
        asm volatile("barrier.cluster.arrive.aligned;" ::: "memory");

        if (tid < 256){
            float* od2 = out + ((size_t)(n*LS + t))*4096 + (A0 + e_r)*64 + e_c;
            *(float4*)(od2)   = make_float4(hv[0],hv[1],hv[2],hv[3]);
            *(float4*)(od2+4) = make_float4(hv[4],hv[5],hv[6],hv[7]);
            if (t == LS-1){
                float* hl2 = out + (size_t)NB*LS*4096 + (size_t)n*4096 + (A0 + e_r)*64 + e_c;
                *(float4*)(hl2)   = make_float4(hv[0],hv[1],hv[2],hv[3]);
                *(float4*)(hl2+4) = make_float4(hv[4],hv[5],hv[6],hv[7]);
            }
        }
        if (t + 1 < LS){
            #pragma unroll
            for (int k = 0; k < 4; k++){
                int idx = tid + 384*k;
                int gx = idx / 512, rem = idx & 511;
                int row = rem >> 4, off = rem & 15;
                cpa16(smf + XGSf + (buf^1)*XGB + gx*EPP + row*EPS + off*4,
                      xg + ((size_t)(((t+1)*3 + gx)*NB + n))*4096 + (A0+row)*64 + off*4);
            }
        }
        asm volatile("cp.async.commit_group;");

        asm volatile("barrier.cluster.wait.aligned;" ::: "memory");
        buf ^= 1; hb ^= 1;
    }

    // c_last (own rows)
    if (tid < 256){
        float* cl = out + (size_t)NB*LS*4096 + (size_t)NB*4096
                        + (size_t)n*4096 + (A0 + e_r)*64 + e_c;
        *(float4*)(cl)   = make_float4(cst[0],cst[1],cst[2],cst[3]);
        *(float4*)(cl+4) = make_float4(cst[4],cst[5],cst[6],cst[7]);
    }
}

// ---------------------------------------------------------------------------
extern "C" void kernel_launch(void* const* d_in, const int* in_sizes, int n_in,
                              void* d_out, int out_size)
{
    const float* x   = (const float*)d_in[0];
    const float* Ww1 = (const float*)d_in[1];
    const float* Ww2 = (const float*)d_in[2];
    const float* Wu1 = (const float*)d_in[3];
    const float* Wu2 = (const float*)d_in[4];
    float* out = (float*)d_out;

    float* xg = nullptr;
    cudaGetSymbolAddress((void**)&xg, g_xg);

    cudaFuncSetAttribute(phase1_mma, cudaFuncAttributeMaxDynamicSharedMemorySize, (int)P1_BYTES);
    cudaFuncSetAttribute(phase2_mma, cudaFuncAttributeMaxDynamicSharedMemorySize, (int)R2_BYTES);

    phase1_mma<<<148, 384, P1_BYTES>>>(x, Ww1, Ww2, xg);
    phase2_mma<<<2 * NB, 384, R2_BYTES>>>(Wu1, Wu2, xg, out);
}